// round 10
// baseline (speedup 1.0000x reference)
#include <cuda_runtime.h>
#include <cuda_fp16.h>
#include <cstdint>

#define NMAX 50048
#define EMAX 400000

__device__ float g_denom[NMAX];
__device__ float g_aggr[(size_t)NMAX * 128];
// packed fp16 weights: per 16-K slab, [NOUT][24] halves (48B rows)
__device__ __align__(16) unsigned char g_wpack[1093632];

#define OFF_MW1 0u
#define OFF_MW2 208896u
#define OFF_MW3 405504u
#define OFF_AW1 503808u
#define OFF_AW2 552960u
#define OFF_UW1 602112u
#define OFF_UW2 798720u
#define OFF_UW3 995328u

__device__ __forceinline__ uint32_t smem_u32(const void* p) {
    return (uint32_t)__cvta_generic_to_shared(p);
}
__device__ __forceinline__ void ldsm4(uint32_t& r0, uint32_t& r1,
                                      uint32_t& r2, uint32_t& r3, uint32_t a) {
    asm volatile("ldmatrix.sync.aligned.m8n8.x4.shared.b16 {%0,%1,%2,%3}, [%4];"
                 : "=r"(r0), "=r"(r1), "=r"(r2), "=r"(r3) : "r"(a));
}
__device__ __forceinline__ void ldsm2(uint32_t& r0, uint32_t& r1, uint32_t a) {
    asm volatile("ldmatrix.sync.aligned.m8n8.x2.shared.b16 {%0,%1}, [%2];"
                 : "=r"(r0), "=r"(r1) : "r"(a));
}
__device__ __forceinline__ void mma_f16(float c[4],
    uint32_t a0, uint32_t a1, uint32_t a2, uint32_t a3, uint32_t b0, uint32_t b1)
{
    asm volatile(
        "mma.sync.aligned.m16n8k16.row.col.f32.f16.f16.f32 "
        "{%0,%1,%2,%3}, {%4,%5,%6,%7}, {%8,%9}, {%0,%1,%2,%3};"
        : "+f"(c[0]), "+f"(c[1]), "+f"(c[2]), "+f"(c[3])
        : "r"(a0), "r"(a1), "r"(a2), "r"(a3), "r"(b0), "r"(b1));
}

// per-warp weight region: 3 stages x 768 B (max NW=16 cols x 48 B)
#define WSTAGE 768
#define WREGION 2304
#define NWARP 16
#define NTHREAD 512

// ---------------------------------------------------------------------------
// Warp-autonomous fp16 MLP layer over a 64-row tile, 16 warps.
// Each warp owns cols [warp*NW, (warp+1)*NW), NW = NOUT/16 (16 or 8),
// all 64 rows (4 m16 tiles). B loaded once per slab (ldsm4 or ldsm2),
// A fragments reloaded per m-tile (keeps per-thread registers ~45).
// Per-warp triple-buffered cp.async weight stream: no block barriers in K.
// ---------------------------------------------------------------------------
template<int K, int NOUT, bool RELU, int LDIN, int LDOUT>
__device__ __forceinline__ void mma_layer(
    const __half* __restrict__ sIn, const unsigned char* __restrict__ Wp,
    const float* __restrict__ Bv, __half* __restrict__ sOut,
    unsigned char* __restrict__ sWbase,
    float* __restrict__ gOut, int row0, int rowlim)
{
    constexpr int NSLAB = K / 16;
    constexpr int NW = NOUT / NWARP;   // 16 or 8
    constexpr int NT = NW / 8;         // 2 or 1
    constexpr int WCH = NW * 48 / 16;  // 48 or 24
    const int tid = threadIdx.x, lane = tid & 31, warp = tid >> 5;
    const int n0 = warp * NW;
    unsigned char* wb = sWbase + warp * WREGION;
    const int g = lane >> 2, tg = lane & 3;
    const int a_row = (lane & 7) + ((lane >> 3) & 1) * 8;
    const int a_k   = (lane >> 4) * 8;

    auto issue = [&](int s) {
        if (s < NSLAB) {
            const unsigned char* src = Wp + ((size_t)s * NOUT + n0) * 48;
            unsigned char* dst = wb + (s % 3) * WSTAGE;
#pragma unroll
            for (int c = lane; c < WCH; c += 32) {
                uint32_t da = smem_u32(dst + c * 16);
                asm volatile("cp.async.ca.shared.global [%0], [%1], 16;"
                             :: "r"(da), "l"(src + c * 16));
            }
        }
        asm volatile("cp.async.commit_group;");
    };

    issue(0); issue(1); issue(2);
    __syncthreads();   // sIn ready

    float acc[4][NT][4];
#pragma unroll
    for (int mt = 0; mt < 4; mt++)
#pragma unroll
        for (int nt = 0; nt < NT; nt++)
#pragma unroll
            for (int q = 0; q < 4; q++) acc[mt][nt][q] = 0.f;

    for (int s = 0; s < NSLAB; s++) {
        asm volatile("cp.async.wait_group 2;" ::: "memory");
        __syncwarp();
        const unsigned char* buf = wb + (s % 3) * WSTAGE;
        const int kc = s * 16;
        uint32_t B0, B1, B2, B3;
        if constexpr (NT == 2) {
            int b_n = ((lane >> 4) & 1) * 8 + (lane & 7);
            int b_k = ((lane >> 3) & 1) * 8;
            ldsm4(B0, B1, B2, B3, smem_u32(buf + b_n * 48 + b_k * 2));
        } else {
            int b_n = lane & 7;
            int b_k = ((lane >> 3) & 1) * 8;
            ldsm2(B0, B1, smem_u32(buf + b_n * 48 + b_k * 2));
            B2 = B3 = 0;
        }
#pragma unroll
        for (int mt = 0; mt < 4; mt++) {
            uint32_t A0, A1, A2, A3;
            ldsm4(A0, A1, A2, A3,
                  smem_u32(sIn + (mt * 16 + a_row) * LDIN + kc + a_k));
            mma_f16(acc[mt][0], A0, A1, A2, A3, B0, B1);
            if constexpr (NT == 2)
                mma_f16(acc[mt][1], A0, A1, A2, A3, B2, B3);
        }
        issue(s + 3);
    }

#pragma unroll
    for (int nt = 0; nt < NT; nt++) {
        int c = n0 + nt * 8 + 2 * tg;
        float b0 = __ldg(Bv + c), b1 = __ldg(Bv + c + 1);
#pragma unroll
        for (int mt = 0; mt < 4; mt++) {
#pragma unroll
            for (int h = 0; h < 2; h++) {
                int r = mt * 16 + g + h * 8;
                float v0 = acc[mt][nt][h * 2 + 0] + b0;
                float v1 = acc[mt][nt][h * 2 + 1] + b1;
                if (RELU) { v0 = fmaxf(v0, 0.f); v1 = fmaxf(v1, 0.f); }
                *(__half2*)(sOut + r * LDOUT + c) = __floats2half2_rn(v0, v1);
                if (gOut != nullptr && row0 + r < rowlim)
                    *(float2*)(gOut + (size_t)(row0 + r) * NOUT + c) =
                        make_float2(v0, v1);
            }
        }
    }
    __syncthreads();
}

// ---------------------------------------------------------------------------
// G2 variant (NOUT=128, NW=8, NT=1): no smem output; gate dot folded into
// epilogue. Partials quad-reduced, written to sdot[row*16 + warp].
// ---------------------------------------------------------------------------
template<int K, int LDIN>
__device__ __forceinline__ void mma_layer_dot(
    const __half* __restrict__ sIn, const unsigned char* __restrict__ Wp,
    const float* __restrict__ Bv, const float* __restrict__ aw3,
    float* __restrict__ sdot, unsigned char* __restrict__ sWbase)
{
    constexpr int NOUT = 128, NSLAB = K / 16, NW = 8, WCH = 24;
    const int tid = threadIdx.x, lane = tid & 31, warp = tid >> 5;
    const int n0 = warp * NW;
    unsigned char* wb = sWbase + warp * WREGION;
    const int g = lane >> 2, tg = lane & 3;
    const int a_row = (lane & 7) + ((lane >> 3) & 1) * 8;
    const int a_k   = (lane >> 4) * 8;

    auto issue = [&](int s) {
        if (s < NSLAB) {
            const unsigned char* src = Wp + ((size_t)s * NOUT + n0) * 48;
            unsigned char* dst = wb + (s % 3) * WSTAGE;
#pragma unroll
            for (int c = lane; c < WCH; c += 32) {
                uint32_t da = smem_u32(dst + c * 16);
                asm volatile("cp.async.ca.shared.global [%0], [%1], 16;"
                             :: "r"(da), "l"(src + c * 16));
            }
        }
        asm volatile("cp.async.commit_group;");
    };

    issue(0); issue(1); issue(2);
    __syncthreads();

    float acc[4][4];
#pragma unroll
    for (int mt = 0; mt < 4; mt++)
#pragma unroll
        for (int q = 0; q < 4; q++) acc[mt][q] = 0.f;

    for (int s = 0; s < NSLAB; s++) {
        asm volatile("cp.async.wait_group 2;" ::: "memory");
        __syncwarp();
        const unsigned char* buf = wb + (s % 3) * WSTAGE;
        const int kc = s * 16;
        uint32_t B0, B1;
        {
            int b_n = lane & 7;
            int b_k = ((lane >> 3) & 1) * 8;
            ldsm2(B0, B1, smem_u32(buf + b_n * 48 + b_k * 2));
        }
#pragma unroll
        for (int mt = 0; mt < 4; mt++) {
            uint32_t A0, A1, A2, A3;
            ldsm4(A0, A1, A2, A3,
                  smem_u32(sIn + (mt * 16 + a_row) * LDIN + kc + a_k));
            mma_f16(acc[mt], A0, A1, A2, A3, B0, B1);
        }
        issue(s + 3);
    }

    // epilogue: dot with aw3 over this warp's 8 cols, per row
    int c = n0 + 2 * tg;
    float b0 = __ldg(Bv + c), b1 = __ldg(Bv + c + 1);
    float a0 = __ldg(aw3 + c), a1 = __ldg(aw3 + c + 1);
#pragma unroll
    for (int mt = 0; mt < 4; mt++) {
#pragma unroll
        for (int h = 0; h < 2; h++) {
            float v0 = acc[mt][h * 2 + 0] + b0;
            float v1 = acc[mt][h * 2 + 1] + b1;
            float dp = v0 * a0 + v1 * a1;
            dp += __shfl_xor_sync(0xffffffffu, dp, 1);
            dp += __shfl_xor_sync(0xffffffffu, dp, 2);
            if (tg == 0) {
                int r = mt * 16 + g + h * 8;
                sdot[r * 16 + warp] = dp;
            }
        }
    }
    __syncthreads();
}

// ---------------------------------------------------------------------------
// Fused pack + init kernel (one launch).
// ---------------------------------------------------------------------------
__device__ __forceinline__ void pack_one(const float* src, int idx, int N,
                                         unsigned int off) {
    int k = idx / N, n = idx - k * N;
    *(__half*)(g_wpack + off + (((size_t)(k >> 4) * N + n) * 24 + (k & 15)) * 2) =
        __float2half_rn(src[idx]);
}
__global__ void pack_init_kernel(
    const float* __restrict__ mw1, const float* __restrict__ mw2,
    const float* __restrict__ mw3, const float* __restrict__ aw1,
    const float* __restrict__ aw2, const float* __restrict__ uw1,
    const float* __restrict__ uw2, const float* __restrict__ uw3, int N)
{
    int idx = blockIdx.x * blockDim.x + threadIdx.x;
    if      (idx <  69632) pack_one(mw1, idx,          256, OFF_MW1);
    else if (idx < 135168) pack_one(mw2, idx -  69632, 256, OFF_MW2);
    else if (idx < 167936) pack_one(mw3, idx - 135168, 128, OFF_MW3);
    else if (idx < 184320) pack_one(aw1, idx - 167936, 128, OFF_AW1);
    else if (idx < 200704) pack_one(aw2, idx - 184320, 128, OFF_AW2);
    else if (idx < 266240) pack_one(uw1, idx - 200704, 256, OFF_UW1);
    else if (idx < 331776) pack_one(uw2, idx - 266240, 256, OFF_UW2);
    else if (idx < 364544) pack_one(uw3, idx - 331776, 128, OFF_UW3);
    if (idx < N * 128) g_aggr[idx] = 0.f;
    if (idx < N) g_denom[idx] = 0.f;
}

// ---------------------------------------------------------------------------
// edge kernel: full fusion. 512 threads, 16 warps.
// smem: sA 35840 | sB 33792 | sW 36864 | sdot 4096 | swexp 256 = 110848 B
// ---------------------------------------------------------------------------
__global__ __launch_bounds__(NTHREAD, 2)
void edge_kernel(
    const float* __restrict__ nodes, const float* __restrict__ edges,
    const int* __restrict__ senders, const int* __restrict__ receivers,
    const float* __restrict__ b1, const float* __restrict__ b2,
    const float* __restrict__ b3, const float* __restrict__ ab1,
    const float* __restrict__ ab2,
    const float* __restrict__ aw3, const float* __restrict__ ab3, int E)
{
    extern __shared__ unsigned char smem[];
    __half* sA = (__half*)smem;                    // stride 280 (or 136)
    __half* sB = (__half*)(smem + 35840);          // stride 264 (or 136)
    unsigned char* sW = smem + 69632;
    float* sdot = (float*)(smem + 106496);         // [64][16]
    float* swexp = (float*)(smem + 110592);        // [64]

    const int tid = threadIdx.x, lane = tid & 31, warp = tid >> 5;
    const int e0 = blockIdx.x * 64;

#pragma unroll
    for (int i = 0; i < 4; i++) {
        int e = warp * 4 + i;
        int eg = e0 + e;
        int egc = eg < E ? eg : E - 1;
        int s = senders[egc], r = receivers[egc];
        __half* dst = sA + e * 280;
        if (lane < 4) {
            float4 v = *(const float4*)(edges + (size_t)egc * 16 + lane * 4);
            *(__half2*)(dst + lane * 4)     = __floats2half2_rn(v.x, v.y);
            *(__half2*)(dst + lane * 4 + 2) = __floats2half2_rn(v.z, v.w);
        }
        float4 vs = *(const float4*)(nodes + (size_t)s * 128 + lane * 4);
        *(__half2*)(dst + 16 + lane * 4)     = __floats2half2_rn(vs.x, vs.y);
        *(__half2*)(dst + 16 + lane * 4 + 2) = __floats2half2_rn(vs.z, vs.w);
        float4 vr = *(const float4*)(nodes + (size_t)r * 128 + lane * 4);
        *(__half2*)(dst + 144 + lane * 4)     = __floats2half2_rn(vr.x, vr.y);
        *(__half2*)(dst + 144 + lane * 4 + 2) = __floats2half2_rn(vr.z, vr.w);
    }

    mma_layer<272, 256, true , 280, 264>(sA, g_wpack + OFF_MW1, b1, sB, sW, nullptr, 0, 0);
    mma_layer<256, 256, false, 264, 280>(sB, g_wpack + OFF_MW2, b2, sA, sW, nullptr, 0, 0);
    mma_layer<256, 128, false, 280, 136>(sA, g_wpack + OFF_MW3, b3, sB, sW, nullptr, 0, 0);
    mma_layer<128, 128, true , 136, 136>(sB, g_wpack + OFF_AW1, ab1, sA, sW, nullptr, 0, 0);
    mma_layer_dot<128, 136>(sA, g_wpack + OFF_AW2, ab2, aw3, sdot, sW);

    // finalize gates: w = exp(gate) (max-free softmax; exact in real arith)
    if (tid < 64) {
        int eg = e0 + tid;
        float w = 0.f;
        if (eg < E) {
            float gate = __ldg(ab3);
#pragma unroll
            for (int j = 0; j < 16; j++) gate += sdot[tid * 16 + j];
            w = expf(gate);
            atomicAdd(&g_denom[receivers[eg]], w);
        }
        swexp[tid] = w;
    }
    __syncthreads();

    // scatter: aggr[recv] += w * msg (msgs are fp16 in sB, stride 136)
#pragma unroll
    for (int i = 0; i < 4; i++) {
        int e = warp * 4 + i;
        int eg = e0 + e;
        if (eg >= E) continue;
        float w = swexp[e];
        int r = receivers[eg];
        __half2 p0 = *(__half2*)(sB + e * 136 + lane * 4);
        __half2 p1 = *(__half2*)(sB + e * 136 + lane * 4 + 2);
        float2 f0 = __half22float2(p0), f1 = __half22float2(p1);
        float* dst = g_aggr + (size_t)r * 128 + lane * 4;
        atomicAdd(dst + 0, w * f0.x);
        atomicAdd(dst + 1, w * f0.y);
        atomicAdd(dst + 2, w * f1.x);
        atomicAdd(dst + 3, w * f1.y);
    }
}

// ---------------------------------------------------------------------------
// node kernel: 512 threads; normalizes aggr by denom at gather.
// smem: sA 33792 | sB 33792 | sW 36864 = 104448 B
// ---------------------------------------------------------------------------
__global__ __launch_bounds__(NTHREAD, 2)
void node_kernel(
    const float* __restrict__ nodes,
    const float* __restrict__ ub1, const float* __restrict__ ub2,
    const float* __restrict__ ub3, float* __restrict__ out, int N)
{
    extern __shared__ unsigned char smem[];
    __half* sA = (__half*)smem;                    // stride 264
    __half* sB = (__half*)(smem + 33792);
    unsigned char* sW = smem + 67584;

    const int tid = threadIdx.x, lane = tid & 31, warp = tid >> 5;
    const int n0 = blockIdx.x * 64;

#pragma unroll
    for (int i = 0; i < 4; i++) {
        int e = warp * 4 + i;
        int n = n0 + e;
        __half* dst = sA + e * 264;
        if (n < N) {
            float4 v0 = *(const float4*)(nodes + (size_t)n * 128 + lane * 4);
            *(__half2*)(dst + lane * 4)     = __floats2half2_rn(v0.x, v0.y);
            *(__half2*)(dst + lane * 4 + 2) = __floats2half2_rn(v0.z, v0.w);
            float d = g_denom[n];
            float inv = d > 0.f ? 1.f / d : 0.f;
            float4 v1 = *(const float4*)(g_aggr + (size_t)n * 128 + lane * 4);
            *(__half2*)(dst + 128 + lane * 4)     = __floats2half2_rn(inv * v1.x, inv * v1.y);
            *(__half2*)(dst + 128 + lane * 4 + 2) = __floats2half2_rn(inv * v1.z, inv * v1.w);
        } else {
            *(float2*)(dst + lane * 4) = make_float2(0.f, 0.f);
            *(float2*)(dst + 128 + lane * 4) = make_float2(0.f, 0.f);
        }
    }

    mma_layer<256, 256, true , 264, 264>(sA, g_wpack + OFF_UW1, ub1, sB, sW, nullptr, 0, 0);
    mma_layer<256, 256, false, 264, 264>(sB, g_wpack + OFF_UW2, ub2, sA, sW, nullptr, 0, 0);
    mma_layer<256, 128, false, 264, 136>(sA, g_wpack + OFF_UW3, ub3, sB, sW, out, n0, N);
}

// ---------------------------------------------------------------------------
extern "C" void kernel_launch(void* const* d_in, const int* in_sizes, int n_in,
                              void* d_out, int out_size)
{
    const float* nodes     = (const float*)d_in[0];
    const float* edges     = (const float*)d_in[1];
    const int*   senders   = (const int*)  d_in[2];
    const int*   receivers = (const int*)  d_in[3];
    const float* mw1 = (const float*)d_in[4];  const float* mb1 = (const float*)d_in[5];
    const float* mw2 = (const float*)d_in[6];  const float* mb2 = (const float*)d_in[7];
    const float* mw3 = (const float*)d_in[8];  const float* mb3 = (const float*)d_in[9];
    const float* aw1 = (const float*)d_in[10]; const float* ab1 = (const float*)d_in[11];
    const float* aw2 = (const float*)d_in[12]; const float* ab2 = (const float*)d_in[13];
    const float* aw3 = (const float*)d_in[14]; const float* ab3 = (const float*)d_in[15];
    const float* uw1 = (const float*)d_in[16]; const float* ub1 = (const float*)d_in[17];
    const float* uw2 = (const float*)d_in[18]; const float* ub2 = (const float*)d_in[19];
    const float* uw3 = (const float*)d_in[20]; const float* ub3 = (const float*)d_in[21];
    float* out = (float*)d_out;

    const int N = in_sizes[0] / 128;
    const int E = in_sizes[2];

    const int EDGE_SMEM = 110848;
    const int NODE_SMEM = 104448;
    cudaFuncSetAttribute(edge_kernel, cudaFuncAttributeMaxDynamicSharedMemorySize, EDGE_SMEM);
    cudaFuncSetAttribute(node_kernel, cudaFuncAttributeMaxDynamicSharedMemorySize, NODE_SMEM);

    pack_init_kernel<<<(N * 128 + 255) / 256, 256>>>(
        mw1, mw2, mw3, aw1, aw2, uw1, uw2, uw3, N);

    edge_kernel<<<(E + 63) / 64, NTHREAD, EDGE_SMEM>>>(
        nodes, edges, senders, receivers,
        mb1, mb2, mb3, ab1, ab2, aw3, ab3, E);

    node_kernel<<<(N + 63) / 64, NTHREAD, NODE_SMEM>>>(
        nodes, ub1, ub2, ub3, out, N);
}

// round 11
// speedup vs baseline: 1.3402x; 1.3402x over previous
#include <cuda_runtime.h>
#include <cuda_fp16.h>
#include <cstdint>

#define NMAX 50048
#define EMAX 400000

__device__ float g_denom[NMAX];
__device__ float g_aggr[(size_t)NMAX * 128];
// packed fp16 weights: per 16-K slab, [NOUT][24] halves (48B rows)
__device__ __align__(16) unsigned char g_wpack[1093632];

#define OFF_MW1 0u
#define OFF_MW2 208896u
#define OFF_MW3 405504u
#define OFF_AW1 503808u
#define OFF_AW2 552960u
#define OFF_UW1 602112u
#define OFF_UW2 798720u
#define OFF_UW3 995328u

__device__ __forceinline__ uint32_t smem_u32(const void* p) {
    return (uint32_t)__cvta_generic_to_shared(p);
}
__device__ __forceinline__ void ldsm4(uint32_t& r0, uint32_t& r1,
                                      uint32_t& r2, uint32_t& r3, uint32_t a) {
    asm volatile("ldmatrix.sync.aligned.m8n8.x4.shared.b16 {%0,%1,%2,%3}, [%4];"
                 : "=r"(r0), "=r"(r1), "=r"(r2), "=r"(r3) : "r"(a));
}
__device__ __forceinline__ void mma_f16(float c[4],
    uint32_t a0, uint32_t a1, uint32_t a2, uint32_t a3, uint32_t b0, uint32_t b1)
{
    asm volatile(
        "mma.sync.aligned.m16n8k16.row.col.f32.f16.f16.f32 "
        "{%0,%1,%2,%3}, {%4,%5,%6,%7}, {%8,%9}, {%0,%1,%2,%3};"
        : "+f"(c[0]), "+f"(c[1]), "+f"(c[2]), "+f"(c[3])
        : "r"(a0), "r"(a1), "r"(a2), "r"(a3), "r"(b0), "r"(b1));
}

#define WSTAGE 1536
#define WREGION 4608

// ---------------------------------------------------------------------------
// Warp-autonomous fp16 MLP layer over 64 rows, 8 warps (proven R9 config).
// Each warp owns cols [warp*NW, (warp+1)*NW), NW = NOUT/8, all 64 rows.
// Weights stream per-warp via cp.async into a private triple-buffered region.
// ---------------------------------------------------------------------------
template<int K, int NOUT, bool RELU, int LDIN, int LDOUT>
__device__ __forceinline__ void mma_layer(
    const __half* __restrict__ sIn, const unsigned char* __restrict__ Wp,
    const float* __restrict__ Bv, __half* __restrict__ sOut,
    unsigned char* __restrict__ sWbase,
    float* __restrict__ gOut, int row0, int rowlim)
{
    constexpr int NSLAB = K / 16;
    constexpr int NW = NOUT / 8;
    constexpr int NT = NW / 8;
    constexpr int WCH = NW * 48 / 16;
    const int tid = threadIdx.x, lane = tid & 31, warp = tid >> 5;
    const int n0 = warp * NW;
    unsigned char* wb = sWbase + warp * WREGION;
    const int g = lane >> 2, tg = lane & 3;
    const int a_row = (lane & 7) + ((lane >> 3) & 1) * 8;
    const int a_k   = (lane >> 4) * 8;
    const int b_n   = ((lane >> 4) & 1) * 8 + (lane & 7);
    const int b_k   = ((lane >> 3) & 1) * 8;

    auto issue = [&](int s) {
        if (s < NSLAB) {
            const unsigned char* src = Wp + ((size_t)s * NOUT + n0) * 48;
            unsigned char* dst = wb + (s % 3) * WSTAGE;
#pragma unroll
            for (int c = lane; c < WCH; c += 32) {
                uint32_t da = smem_u32(dst + c * 16);
                asm volatile("cp.async.ca.shared.global [%0], [%1], 16;"
                             :: "r"(da), "l"(src + c * 16));
            }
        }
        asm volatile("cp.async.commit_group;");
    };

    issue(0); issue(1); issue(2);
    __syncthreads();   // sIn ready

    float acc[4][NT][4];
#pragma unroll
    for (int mt = 0; mt < 4; mt++)
#pragma unroll
        for (int nt = 0; nt < NT; nt++)
#pragma unroll
            for (int q = 0; q < 4; q++) acc[mt][nt][q] = 0.f;

    for (int s = 0; s < NSLAB; s++) {
        asm volatile("cp.async.wait_group 2;" ::: "memory");
        __syncwarp();
        const unsigned char* buf = wb + (s % 3) * WSTAGE;
        const int kc = s * 16;
        uint32_t A[4][4];
#pragma unroll
        for (int mt = 0; mt < 4; mt++)
            ldsm4(A[mt][0], A[mt][1], A[mt][2], A[mt][3],
                  smem_u32(sIn + (mt * 16 + a_row) * LDIN + kc + a_k));
#pragma unroll
        for (int ng = 0; ng < NT / 2; ng++) {
            uint32_t B0, B1, B2, B3;
            ldsm4(B0, B1, B2, B3, smem_u32(buf + (ng * 16 + b_n) * 48 + b_k * 2));
#pragma unroll
            for (int mt = 0; mt < 4; mt++) {
                mma_f16(acc[mt][2 * ng],     A[mt][0], A[mt][1], A[mt][2], A[mt][3], B0, B1);
                mma_f16(acc[mt][2 * ng + 1], A[mt][0], A[mt][1], A[mt][2], A[mt][3], B2, B3);
            }
        }
        issue(s + 3);
    }

#pragma unroll
    for (int nt = 0; nt < NT; nt++) {
        int c = n0 + nt * 8 + 2 * tg;
        float b0 = __ldg(Bv + c), b1 = __ldg(Bv + c + 1);
#pragma unroll
        for (int mt = 0; mt < 4; mt++) {
#pragma unroll
            for (int h = 0; h < 2; h++) {
                int r = mt * 16 + g + h * 8;
                float v0 = acc[mt][nt][h * 2 + 0] + b0;
                float v1 = acc[mt][nt][h * 2 + 1] + b1;
                if (RELU) { v0 = fmaxf(v0, 0.f); v1 = fmaxf(v1, 0.f); }
                *(__half2*)(sOut + r * LDOUT + c) = __floats2half2_rn(v0, v1);
                if (gOut != nullptr && row0 + r < rowlim)
                    *(float2*)(gOut + (size_t)(row0 + r) * NOUT + c) =
                        make_float2(v0, v1);
            }
        }
    }
    __syncthreads();
}

// ---------------------------------------------------------------------------
// G2 variant: no smem output; gate dot folded into epilogue (R9-proven).
// ---------------------------------------------------------------------------
template<int K, int LDIN>
__device__ __forceinline__ void mma_layer_dot(
    const __half* __restrict__ sIn, const unsigned char* __restrict__ Wp,
    const float* __restrict__ Bv, const float* __restrict__ aw3,
    float* __restrict__ sdot, unsigned char* __restrict__ sWbase)
{
    constexpr int NOUT = 128, NSLAB = K / 16, NW = 16, NT = 2, WCH = NW * 48 / 16;
    const int tid = threadIdx.x, lane = tid & 31, warp = tid >> 5;
    const int n0 = warp * NW;
    unsigned char* wb = sWbase + warp * WREGION;
    const int g = lane >> 2, tg = lane & 3;
    const int a_row = (lane & 7) + ((lane >> 3) & 1) * 8;
    const int a_k   = (lane >> 4) * 8;
    const int b_n   = ((lane >> 4) & 1) * 8 + (lane & 7);
    const int b_k   = ((lane >> 3) & 1) * 8;

    auto issue = [&](int s) {
        if (s < NSLAB) {
            const unsigned char* src = Wp + ((size_t)s * NOUT + n0) * 48;
            unsigned char* dst = wb + (s % 3) * WSTAGE;
#pragma unroll
            for (int c = lane; c < WCH; c += 32) {
                uint32_t da = smem_u32(dst + c * 16);
                asm volatile("cp.async.ca.shared.global [%0], [%1], 16;"
                             :: "r"(da), "l"(src + c * 16));
            }
        }
        asm volatile("cp.async.commit_group;");
    };

    issue(0); issue(1); issue(2);
    __syncthreads();

    float acc[4][NT][4];
#pragma unroll
    for (int mt = 0; mt < 4; mt++)
#pragma unroll
        for (int nt = 0; nt < NT; nt++)
#pragma unroll
            for (int q = 0; q < 4; q++) acc[mt][nt][q] = 0.f;

    for (int s = 0; s < NSLAB; s++) {
        asm volatile("cp.async.wait_group 2;" ::: "memory");
        __syncwarp();
        const unsigned char* buf = wb + (s % 3) * WSTAGE;
        const int kc = s * 16;
        uint32_t A[4][4];
#pragma unroll
        for (int mt = 0; mt < 4; mt++)
            ldsm4(A[mt][0], A[mt][1], A[mt][2], A[mt][3],
                  smem_u32(sIn + (mt * 16 + a_row) * LDIN + kc + a_k));
        uint32_t B0, B1, B2, B3;
        ldsm4(B0, B1, B2, B3, smem_u32(buf + b_n * 48 + b_k * 2));
#pragma unroll
        for (int mt = 0; mt < 4; mt++) {
            mma_f16(acc[mt][0], A[mt][0], A[mt][1], A[mt][2], A[mt][3], B0, B1);
            mma_f16(acc[mt][1], A[mt][0], A[mt][1], A[mt][2], A[mt][3], B2, B3);
        }
        issue(s + 3);
    }

    float dp[4][2];
#pragma unroll
    for (int mt = 0; mt < 4; mt++) { dp[mt][0] = 0.f; dp[mt][1] = 0.f; }
#pragma unroll
    for (int nt = 0; nt < NT; nt++) {
        int c = n0 + nt * 8 + 2 * tg;
        float b0 = __ldg(Bv + c), b1 = __ldg(Bv + c + 1);
        float a0 = __ldg(aw3 + c), a1 = __ldg(aw3 + c + 1);
#pragma unroll
        for (int mt = 0; mt < 4; mt++) {
#pragma unroll
            for (int h = 0; h < 2; h++) {
                float v0 = acc[mt][nt][h * 2 + 0] + b0;
                float v1 = acc[mt][nt][h * 2 + 1] + b1;
                dp[mt][h] += v0 * a0 + v1 * a1;
            }
        }
    }
#pragma unroll
    for (int mt = 0; mt < 4; mt++)
#pragma unroll
        for (int h = 0; h < 2; h++) {
            dp[mt][h] += __shfl_xor_sync(0xffffffffu, dp[mt][h], 1);
            dp[mt][h] += __shfl_xor_sync(0xffffffffu, dp[mt][h], 2);
            if (tg == 0) {
                int r = mt * 16 + g + h * 8;
                sdot[r * 8 + warp] = dp[mt][h];
            }
        }
    __syncthreads();
}

// ---------------------------------------------------------------------------
// Fused pack + init kernel (one launch; measured 18 us in R10).
// ---------------------------------------------------------------------------
__device__ __forceinline__ void pack_one(const float* src, int idx, int N,
                                         unsigned int off) {
    int k = idx / N, n = idx - k * N;
    *(__half*)(g_wpack + off + (((size_t)(k >> 4) * N + n) * 24 + (k & 15)) * 2) =
        __float2half_rn(src[idx]);
}
__global__ void pack_init_kernel(
    const float* __restrict__ mw1, const float* __restrict__ mw2,
    const float* __restrict__ mw3, const float* __restrict__ aw1,
    const float* __restrict__ aw2, const float* __restrict__ uw1,
    const float* __restrict__ uw2, const float* __restrict__ uw3, int N)
{
    int idx = blockIdx.x * blockDim.x + threadIdx.x;
    if      (idx <  69632) pack_one(mw1, idx,          256, OFF_MW1);
    else if (idx < 135168) pack_one(mw2, idx -  69632, 256, OFF_MW2);
    else if (idx < 167936) pack_one(mw3, idx - 135168, 128, OFF_MW3);
    else if (idx < 184320) pack_one(aw1, idx - 167936, 128, OFF_AW1);
    else if (idx < 200704) pack_one(aw2, idx - 184320, 128, OFF_AW2);
    else if (idx < 266240) pack_one(uw1, idx - 200704, 256, OFF_UW1);
    else if (idx < 331776) pack_one(uw2, idx - 266240, 256, OFF_UW2);
    else if (idx < 364544) pack_one(uw3, idx - 331776, 128, OFF_UW3);
    if (idx < N * 128) g_aggr[idx] = 0.f;
    if (idx < N) g_denom[idx] = 0.f;
}

// ---------------------------------------------------------------------------
// edge kernel: full fusion (R9-proven). 256 threads, 8 warps.
// smem: sA 35840 | sB 33792 | sW 36864 | sdot 2048 | swexp 256 = 108800 B
// ---------------------------------------------------------------------------
__global__ __launch_bounds__(256, 2)
void edge_kernel(
    const float* __restrict__ nodes, const float* __restrict__ edges,
    const int* __restrict__ senders, const int* __restrict__ receivers,
    const float* __restrict__ b1, const float* __restrict__ b2,
    const float* __restrict__ b3, const float* __restrict__ ab1,
    const float* __restrict__ ab2,
    const float* __restrict__ aw3, const float* __restrict__ ab3, int E)
{
    extern __shared__ unsigned char smem[];
    __half* sA = (__half*)smem;                    // stride 280 (or 136)
    __half* sB = (__half*)(smem + 35840);          // stride 264 (or 136)
    unsigned char* sW = smem + 69632;
    float* sdot = (float*)(smem + 106496);         // [64][8]
    float* swexp = (float*)(smem + 108544);        // [64]

    const int tid = threadIdx.x, lane = tid & 31, warp = tid >> 5;
    const int e0 = blockIdx.x * 64;

#pragma unroll
    for (int i = 0; i < 8; i++) {
        int e = warp * 8 + i;
        int eg = e0 + e;
        int egc = eg < E ? eg : E - 1;
        int s = senders[egc], r = receivers[egc];
        __half* dst = sA + e * 280;
        if (lane < 4) {
            float4 v = *(const float4*)(edges + (size_t)egc * 16 + lane * 4);
            *(__half2*)(dst + lane * 4)     = __floats2half2_rn(v.x, v.y);
            *(__half2*)(dst + lane * 4 + 2) = __floats2half2_rn(v.z, v.w);
        }
        float4 vs = *(const float4*)(nodes + (size_t)s * 128 + lane * 4);
        *(__half2*)(dst + 16 + lane * 4)     = __floats2half2_rn(vs.x, vs.y);
        *(__half2*)(dst + 16 + lane * 4 + 2) = __floats2half2_rn(vs.z, vs.w);
        float4 vr = *(const float4*)(nodes + (size_t)r * 128 + lane * 4);
        *(__half2*)(dst + 144 + lane * 4)     = __floats2half2_rn(vr.x, vr.y);
        *(__half2*)(dst + 144 + lane * 4 + 2) = __floats2half2_rn(vr.z, vr.w);
    }

    mma_layer<272, 256, true , 280, 264>(sA, g_wpack + OFF_MW1, b1, sB, sW, nullptr, 0, 0);
    mma_layer<256, 256, false, 264, 280>(sB, g_wpack + OFF_MW2, b2, sA, sW, nullptr, 0, 0);
    mma_layer<256, 128, false, 280, 136>(sA, g_wpack + OFF_MW3, b3, sB, sW, nullptr, 0, 0);
    mma_layer<128, 128, true , 136, 136>(sB, g_wpack + OFF_AW1, ab1, sA, sW, nullptr, 0, 0);
    mma_layer_dot<128, 136>(sA, g_wpack + OFF_AW2, ab2, aw3, sdot, sW);

    // finalize gates: w = exp(gate) (max-free softmax; exact in real arith)
    if (tid < 64) {
        int eg = e0 + tid;
        float w = 0.f;
        if (eg < E) {
            float gate = __ldg(ab3);
#pragma unroll
            for (int j = 0; j < 8; j++) gate += sdot[tid * 8 + j];
            w = expf(gate);
            atomicAdd(&g_denom[receivers[eg]], w);
        }
        swexp[tid] = w;
    }
    __syncthreads();

    // scatter: aggr[recv] += w * msg (msgs are fp16 in sB, stride 136)
#pragma unroll
    for (int i = 0; i < 8; i++) {
        int e = warp * 8 + i;
        int eg = e0 + e;
        if (eg >= E) continue;
        float w = swexp[e];
        int r = receivers[eg];
        __half2 p0 = *(__half2*)(sB + e * 136 + lane * 4);
        __half2 p1 = *(__half2*)(sB + e * 136 + lane * 4 + 2);
        float2 f0 = __half22float2(p0), f1 = __half22float2(p1);
        float* dst = g_aggr + (size_t)r * 128 + lane * 4;
        atomicAdd(dst + 0, w * f0.x);
        atomicAdd(dst + 1, w * f0.y);
        atomicAdd(dst + 2, w * f1.x);
        atomicAdd(dst + 3, w * f1.y);
    }
}

// ---------------------------------------------------------------------------
// node kernel (R9-proven): normalizes aggr by denom at gather.
// ---------------------------------------------------------------------------
__global__ __launch_bounds__(256, 2)
void node_kernel(
    const float* __restrict__ nodes,
    const float* __restrict__ ub1, const float* __restrict__ ub2,
    const float* __restrict__ ub3, float* __restrict__ out, int N)
{
    extern __shared__ unsigned char smem[];
    __half* sA = (__half*)smem;                    // stride 264
    __half* sB = (__half*)(smem + 33792);
    unsigned char* sW = smem + 67584;

    const int tid = threadIdx.x, lane = tid & 31, warp = tid >> 5;
    const int n0 = blockIdx.x * 64;

#pragma unroll
    for (int i = 0; i < 8; i++) {
        int e = warp * 8 + i;
        int n = n0 + e;
        __half* dst = sA + e * 264;
        if (n < N) {
            float4 v0 = *(const float4*)(nodes + (size_t)n * 128 + lane * 4);
            *(__half2*)(dst + lane * 4)     = __floats2half2_rn(v0.x, v0.y);
            *(__half2*)(dst + lane * 4 + 2) = __floats2half2_rn(v0.z, v0.w);
            float d = g_denom[n];
            float inv = d > 0.f ? 1.f / d : 0.f;
            float4 v1 = *(const float4*)(g_aggr + (size_t)n * 128 + lane * 4);
            *(__half2*)(dst + 128 + lane * 4)     = __floats2half2_rn(inv * v1.x, inv * v1.y);
            *(__half2*)(dst + 128 + lane * 4 + 2) = __floats2half2_rn(inv * v1.z, inv * v1.w);
        } else {
            *(float2*)(dst + lane * 4) = make_float2(0.f, 0.f);
            *(float2*)(dst + 128 + lane * 4) = make_float2(0.f, 0.f);
        }
    }

    mma_layer<256, 256, true , 264, 264>(sA, g_wpack + OFF_UW1, ub1, sB, sW, nullptr, 0, 0);
    mma_layer<256, 256, false, 264, 264>(sB, g_wpack + OFF_UW2, ub2, sA, sW, nullptr, 0, 0);
    mma_layer<256, 128, false, 264, 136>(sA, g_wpack + OFF_UW3, ub3, sB, sW, out, n0, N);
}

// ---------------------------------------------------------------------------
extern "C" void kernel_launch(void* const* d_in, const int* in_sizes, int n_in,
                              void* d_out, int out_size)
{
    const float* nodes     = (const float*)d_in[0];
    const float* edges     = (const float*)d_in[1];
    const int*   senders   = (const int*)  d_in[2];
    const int*   receivers = (const int*)  d_in[3];
    const float* mw1 = (const float*)d_in[4];  const float* mb1 = (const float*)d_in[5];
    const float* mw2 = (const float*)d_in[6];  const float* mb2 = (const float*)d_in[7];
    const float* mw3 = (const float*)d_in[8];  const float* mb3 = (const float*)d_in[9];
    const float* aw1 = (const float*)d_in[10]; const float* ab1 = (const float*)d_in[11];
    const float* aw2 = (const float*)d_in[12]; const float* ab2 = (const float*)d_in[13];
    const float* aw3 = (const float*)d_in[14]; const float* ab3 = (const float*)d_in[15];
    const float* uw1 = (const float*)d_in[16]; const float* ub1 = (const float*)d_in[17];
    const float* uw2 = (const float*)d_in[18]; const float* ub2 = (const float*)d_in[19];
    const float* uw3 = (const float*)d_in[20]; const float* ub3 = (const float*)d_in[21];
    float* out = (float*)d_out;

    const int N = in_sizes[0] / 128;
    const int E = in_sizes[2];

    const int EDGE_SMEM = 108800;
    const int NODE_SMEM = 104448;
    cudaFuncSetAttribute(edge_kernel, cudaFuncAttributeMaxDynamicSharedMemorySize, EDGE_SMEM);
    cudaFuncSetAttribute(node_kernel, cudaFuncAttributeMaxDynamicSharedMemorySize, NODE_SMEM);

    pack_init_kernel<<<(N * 128 + 255) / 256, 256>>>(
        mw1, mw2, mw3, aw1, aw2, uw1, uw2, uw3, N);

    edge_kernel<<<(E + 63) / 64, 256, EDGE_SMEM>>>(
        nodes, edges, senders, receivers,
        mb1, mb2, mb3, ab1, ab2, aw3, ab3, E);

    node_kernel<<<(N + 63) / 64, 256, NODE_SMEM>>>(
        nodes, ub1, ub2, ub3, out, N);
}

// round 12
// speedup vs baseline: 1.5375x; 1.1473x over previous
#include <cuda_runtime.h>
#include <cuda_fp16.h>
#include <cstdint>

#define NMAX 50048
#define EMAX 400000

__device__ float g_denom[NMAX];
__device__ float g_aggr[(size_t)NMAX * 128];
// packed fp16 weights: per 16-K slab, [NOUT][32B] rows, XOR-swizzled halves
__device__ __align__(16) unsigned char g_wpack[729088];

// byte offsets: ceil(K/16) * NOUT * 32
#define OFF_MW1 0u        // 17*256*32
#define OFF_MW2 139264u   // 16*256*32
#define OFF_MW3 270336u   // 16*128*32
#define OFF_AW1 335872u   //  8*128*32
#define OFF_AW2 368640u
#define OFF_UW1 401408u
#define OFF_UW2 532480u
#define OFF_UW3 663552u

__device__ __forceinline__ uint32_t smem_u32(const void* p) {
    return (uint32_t)__cvta_generic_to_shared(p);
}
__device__ __forceinline__ void ldsm4(uint32_t& r0, uint32_t& r1,
                                      uint32_t& r2, uint32_t& r3, uint32_t a) {
    asm volatile("ldmatrix.sync.aligned.m8n8.x4.shared.b16 {%0,%1,%2,%3}, [%4];"
                 : "=r"(r0), "=r"(r1), "=r"(r2), "=r"(r3) : "r"(a));
}
__device__ __forceinline__ void mma_f16(float c[4],
    uint32_t a0, uint32_t a1, uint32_t a2, uint32_t a3, uint32_t b0, uint32_t b1)
{
    asm volatile(
        "mma.sync.aligned.m16n8k16.row.col.f32.f16.f16.f32 "
        "{%0,%1,%2,%3}, {%4,%5,%6,%7}, {%8,%9}, {%0,%1,%2,%3};"
        : "+f"(c[0]), "+f"(c[1]), "+f"(c[2]), "+f"(c[3])
        : "r"(a0), "r"(a1), "r"(a2), "r"(a3), "r"(b0), "r"(b1));
}

// per-warp weight region: 3 stages x 1024 B (max NW=32 rows x 32 B)
#define WSTAGE 1024
#define WREGION 3072

// B-row swizzled byte offset inside a slab strip (row-local), 32 B rows:
// half h (0/1, 16B) xored with bit2 of row -> banks {0,8,16,24,4,12,20,28}
__device__ __forceinline__ uint32_t bswz(int row, int h) {
    return (uint32_t)(row * 32 + ((h ^ ((row >> 2) & 1)) << 4));
}

// ---------------------------------------------------------------------------
// Warp-autonomous fp16 MLP layer over 64 rows, 8 warps (R9 structure).
// Weights: 32B swizzled rows, flat cp.async copy, triple-buffered per warp.
// ---------------------------------------------------------------------------
template<int K, int NOUT, bool RELU, int LDIN, int LDOUT>
__device__ __forceinline__ void mma_layer(
    const __half* __restrict__ sIn, const unsigned char* __restrict__ Wp,
    const float* __restrict__ Bv, __half* __restrict__ sOut,
    unsigned char* __restrict__ sWbase,
    float* __restrict__ gOut, int row0, int rowlim)
{
    constexpr int NSLAB = K / 16;
    constexpr int NW = NOUT / 8;
    constexpr int NT = NW / 8;
    constexpr int WCH = NW * 2;        // 16B chunks per slab strip
    const int tid = threadIdx.x, lane = tid & 31, warp = tid >> 5;
    const int n0 = warp * NW;
    unsigned char* wb = sWbase + warp * WREGION;
    const int g = lane >> 2, tg = lane & 3;
    const int a_row = (lane & 7) + ((lane >> 3) & 1) * 8;
    const int a_k   = (lane >> 4) * 8;
    const int b_n   = ((lane >> 4) & 1) * 8 + (lane & 7);
    const int b_h   = (lane >> 3) & 1;

    auto issue = [&](int s) {
        if (s < NSLAB) {
            const unsigned char* src = Wp + ((size_t)s * NOUT + n0) * 32;
            unsigned char* dst = wb + (s % 3) * WSTAGE;
#pragma unroll
            for (int c = lane; c < WCH; c += 32) {
                uint32_t da = smem_u32(dst + c * 16);
                asm volatile("cp.async.ca.shared.global [%0], [%1], 16;"
                             :: "r"(da), "l"(src + c * 16));
            }
        }
        asm volatile("cp.async.commit_group;");
    };

    issue(0); issue(1); issue(2);
    __syncthreads();   // sIn ready

    float acc[4][NT][4];
#pragma unroll
    for (int mt = 0; mt < 4; mt++)
#pragma unroll
        for (int nt = 0; nt < NT; nt++)
#pragma unroll
            for (int q = 0; q < 4; q++) acc[mt][nt][q] = 0.f;

    for (int s = 0; s < NSLAB; s++) {
        asm volatile("cp.async.wait_group 2;" ::: "memory");
        __syncwarp();
        const unsigned char* buf = wb + (s % 3) * WSTAGE;
        const int kc = s * 16;
        uint32_t A[4][4];
#pragma unroll
        for (int mt = 0; mt < 4; mt++)
            ldsm4(A[mt][0], A[mt][1], A[mt][2], A[mt][3],
                  smem_u32(sIn + (mt * 16 + a_row) * LDIN + kc + a_k));
#pragma unroll
        for (int ng = 0; ng < NT / 2; ng++) {
            uint32_t B0, B1, B2, B3;
            ldsm4(B0, B1, B2, B3, smem_u32(buf + bswz(ng * 16 + b_n, b_h)));
#pragma unroll
            for (int mt = 0; mt < 4; mt++) {
                mma_f16(acc[mt][2 * ng],     A[mt][0], A[mt][1], A[mt][2], A[mt][3], B0, B1);
                mma_f16(acc[mt][2 * ng + 1], A[mt][0], A[mt][1], A[mt][2], A[mt][3], B2, B3);
            }
        }
        issue(s + 3);
    }

#pragma unroll
    for (int nt = 0; nt < NT; nt++) {
        int c = n0 + nt * 8 + 2 * tg;
        float b0 = __ldg(Bv + c), b1 = __ldg(Bv + c + 1);
#pragma unroll
        for (int mt = 0; mt < 4; mt++) {
#pragma unroll
            for (int h = 0; h < 2; h++) {
                int r = mt * 16 + g + h * 8;
                float v0 = acc[mt][nt][h * 2 + 0] + b0;
                float v1 = acc[mt][nt][h * 2 + 1] + b1;
                if (RELU) { v0 = fmaxf(v0, 0.f); v1 = fmaxf(v1, 0.f); }
                *(__half2*)(sOut + r * LDOUT + c) = __floats2half2_rn(v0, v1);
                if (gOut != nullptr && row0 + r < rowlim)
                    *(float2*)(gOut + (size_t)(row0 + r) * NOUT + c) =
                        make_float2(v0, v1);
            }
        }
    }
    __syncthreads();
}

// ---------------------------------------------------------------------------
// G2 variant: gate dot folded into epilogue (R9 structure, swizzled weights).
// ---------------------------------------------------------------------------
template<int K, int LDIN>
__device__ __forceinline__ void mma_layer_dot(
    const __half* __restrict__ sIn, const unsigned char* __restrict__ Wp,
    const float* __restrict__ Bv, const float* __restrict__ aw3,
    float* __restrict__ sdot, unsigned char* __restrict__ sWbase)
{
    constexpr int NOUT = 128, NSLAB = K / 16, NW = 16, NT = 2, WCH = NW * 2;
    const int tid = threadIdx.x, lane = tid & 31, warp = tid >> 5;
    const int n0 = warp * NW;
    unsigned char* wb = sWbase + warp * WREGION;
    const int g = lane >> 2, tg = lane & 3;
    const int a_row = (lane & 7) + ((lane >> 3) & 1) * 8;
    const int a_k   = (lane >> 4) * 8;
    const int b_n   = ((lane >> 4) & 1) * 8 + (lane & 7);
    const int b_h   = (lane >> 3) & 1;

    auto issue = [&](int s) {
        if (s < NSLAB) {
            const unsigned char* src = Wp + ((size_t)s * NOUT + n0) * 32;
            unsigned char* dst = wb + (s % 3) * WSTAGE;
#pragma unroll
            for (int c = lane; c < WCH; c += 32) {
                uint32_t da = smem_u32(dst + c * 16);
                asm volatile("cp.async.ca.shared.global [%0], [%1], 16;"
                             :: "r"(da), "l"(src + c * 16));
            }
        }
        asm volatile("cp.async.commit_group;");
    };

    issue(0); issue(1); issue(2);
    __syncthreads();

    float acc[4][NT][4];
#pragma unroll
    for (int mt = 0; mt < 4; mt++)
#pragma unroll
        for (int nt = 0; nt < NT; nt++)
#pragma unroll
            for (int q = 0; q < 4; q++) acc[mt][nt][q] = 0.f;

    for (int s = 0; s < NSLAB; s++) {
        asm volatile("cp.async.wait_group 2;" ::: "memory");
        __syncwarp();
        const unsigned char* buf = wb + (s % 3) * WSTAGE;
        const int kc = s * 16;
        uint32_t A[4][4];
#pragma unroll
        for (int mt = 0; mt < 4; mt++)
            ldsm4(A[mt][0], A[mt][1], A[mt][2], A[mt][3],
                  smem_u32(sIn + (mt * 16 + a_row) * LDIN + kc + a_k));
        uint32_t B0, B1, B2, B3;
        ldsm4(B0, B1, B2, B3, smem_u32(buf + bswz(b_n, b_h)));
#pragma unroll
        for (int mt = 0; mt < 4; mt++) {
            mma_f16(acc[mt][0], A[mt][0], A[mt][1], A[mt][2], A[mt][3], B0, B1);
            mma_f16(acc[mt][1], A[mt][0], A[mt][1], A[mt][2], A[mt][3], B2, B3);
        }
        issue(s + 3);
    }

    float dp[4][2];
#pragma unroll
    for (int mt = 0; mt < 4; mt++) { dp[mt][0] = 0.f; dp[mt][1] = 0.f; }
#pragma unroll
    for (int nt = 0; nt < NT; nt++) {
        int c = n0 + nt * 8 + 2 * tg;
        float b0 = __ldg(Bv + c), b1 = __ldg(Bv + c + 1);
        float a0 = __ldg(aw3 + c), a1 = __ldg(aw3 + c + 1);
#pragma unroll
        for (int mt = 0; mt < 4; mt++) {
#pragma unroll
            for (int h = 0; h < 2; h++) {
                float v0 = acc[mt][nt][h * 2 + 0] + b0;
                float v1 = acc[mt][nt][h * 2 + 1] + b1;
                dp[mt][h] += v0 * a0 + v1 * a1;
            }
        }
    }
#pragma unroll
    for (int mt = 0; mt < 4; mt++)
#pragma unroll
        for (int h = 0; h < 2; h++) {
            dp[mt][h] += __shfl_xor_sync(0xffffffffu, dp[mt][h], 1);
            dp[mt][h] += __shfl_xor_sync(0xffffffffu, dp[mt][h], 2);
            if (tg == 0) {
                int r = mt * 16 + g + h * 8;
                sdot[r * 8 + warp] = dp[mt][h];
            }
        }
    __syncthreads();
}

// ---------------------------------------------------------------------------
// Fused pack + init kernel. Swizzled 32B-row layout.
// ---------------------------------------------------------------------------
__device__ __forceinline__ void pack_one(const float* src, int idx, int N,
                                         unsigned int off) {
    int k = idx / N, n = idx - k * N;
    int s = k >> 4, h = (k >> 3) & 1, e = k & 7;
    uint32_t b = off + (uint32_t)(s * N + n) * 32u
               + (uint32_t)((h ^ ((n >> 2) & 1)) << 4) + (uint32_t)(e * 2);
    *(__half*)(g_wpack + b) = __float2half_rn(src[idx]);
}
__global__ void pack_init_kernel(
    const float* __restrict__ mw1, const float* __restrict__ mw2,
    const float* __restrict__ mw3, const float* __restrict__ aw1,
    const float* __restrict__ aw2, const float* __restrict__ uw1,
    const float* __restrict__ uw2, const float* __restrict__ uw3, int N)
{
    int idx = blockIdx.x * blockDim.x + threadIdx.x;
    if      (idx <  69632) pack_one(mw1, idx,          256, OFF_MW1);
    else if (idx < 135168) pack_one(mw2, idx -  69632, 256, OFF_MW2);
    else if (idx < 167936) pack_one(mw3, idx - 135168, 128, OFF_MW3);
    else if (idx < 184320) pack_one(aw1, idx - 167936, 128, OFF_AW1);
    else if (idx < 200704) pack_one(aw2, idx - 184320, 128, OFF_AW2);
    else if (idx < 266240) pack_one(uw1, idx - 200704, 256, OFF_UW1);
    else if (idx < 331776) pack_one(uw2, idx - 266240, 256, OFF_UW2);
    else if (idx < 364544) pack_one(uw3, idx - 331776, 128, OFF_UW3);
    if (idx < N * 128) g_aggr[idx] = 0.f;
    if (idx < N) g_denom[idx] = 0.f;
}

// ---------------------------------------------------------------------------
// edge kernel: full fusion. 256 threads, 8 warps.
// smem: sA 35840 | sB 33792 | sW 24576 | sdot 2048 | swexp 256 = 96512 B
// ---------------------------------------------------------------------------
__global__ __launch_bounds__(256, 2)
void edge_kernel(
    const float* __restrict__ nodes, const float* __restrict__ edges,
    const int* __restrict__ senders, const int* __restrict__ receivers,
    const float* __restrict__ b1, const float* __restrict__ b2,
    const float* __restrict__ b3, const float* __restrict__ ab1,
    const float* __restrict__ ab2,
    const float* __restrict__ aw3, const float* __restrict__ ab3, int E)
{
    extern __shared__ unsigned char smem[];
    __half* sA = (__half*)smem;                    // stride 280 (or 136)
    __half* sB = (__half*)(smem + 35840);          // stride 264 (or 136)
    unsigned char* sW = smem + 69632;
    float* sdot = (float*)(smem + 94208);          // [64][8]
    float* swexp = (float*)(smem + 96256);         // [64]

    const int tid = threadIdx.x, lane = tid & 31, warp = tid >> 5;
    const int e0 = blockIdx.x * 64;

#pragma unroll
    for (int i = 0; i < 8; i++) {
        int e = warp * 8 + i;
        int eg = e0 + e;
        int egc = eg < E ? eg : E - 1;
        int s = senders[egc], r = receivers[egc];
        __half* dst = sA + e * 280;
        if (lane < 4) {
            float4 v = *(const float4*)(edges + (size_t)egc * 16 + lane * 4);
            *(__half2*)(dst + lane * 4)     = __floats2half2_rn(v.x, v.y);
            *(__half2*)(dst + lane * 4 + 2) = __floats2half2_rn(v.z, v.w);
        }
        float4 vs = *(const float4*)(nodes + (size_t)s * 128 + lane * 4);
        *(__half2*)(dst + 16 + lane * 4)     = __floats2half2_rn(vs.x, vs.y);
        *(__half2*)(dst + 16 + lane * 4 + 2) = __floats2half2_rn(vs.z, vs.w);
        float4 vr = *(const float4*)(nodes + (size_t)r * 128 + lane * 4);
        *(__half2*)(dst + 144 + lane * 4)     = __floats2half2_rn(vr.x, vr.y);
        *(__half2*)(dst + 144 + lane * 4 + 2) = __floats2half2_rn(vr.z, vr.w);
    }

    mma_layer<272, 256, true , 280, 264>(sA, g_wpack + OFF_MW1, b1, sB, sW, nullptr, 0, 0);
    mma_layer<256, 256, false, 264, 280>(sB, g_wpack + OFF_MW2, b2, sA, sW, nullptr, 0, 0);
    mma_layer<256, 128, false, 280, 136>(sA, g_wpack + OFF_MW3, b3, sB, sW, nullptr, 0, 0);
    mma_layer<128, 128, true , 136, 136>(sB, g_wpack + OFF_AW1, ab1, sA, sW, nullptr, 0, 0);
    mma_layer_dot<128, 136>(sA, g_wpack + OFF_AW2, ab2, aw3, sdot, sW);

    // finalize gates: w = exp(gate) (max-free softmax; exact in real arith)
    if (tid < 64) {
        int eg = e0 + tid;
        float w = 0.f;
        if (eg < E) {
            float gate = __ldg(ab3);
#pragma unroll
            for (int j = 0; j < 8; j++) gate += sdot[tid * 8 + j];
            w = expf(gate);
            atomicAdd(&g_denom[receivers[eg]], w);
        }
        swexp[tid] = w;
    }
    __syncthreads();

    // scatter: aggr[recv] += w * msg (msgs are fp16 in sB, stride 136)
#pragma unroll
    for (int i = 0; i < 8; i++) {
        int e = warp * 8 + i;
        int eg = e0 + e;
        if (eg >= E) continue;
        float w = swexp[e];
        int r = receivers[eg];
        __half2 p0 = *(__half2*)(sB + e * 136 + lane * 4);
        __half2 p1 = *(__half2*)(sB + e * 136 + lane * 4 + 2);
        float2 f0 = __half22float2(p0), f1 = __half22float2(p1);
        float* dst = g_aggr + (size_t)r * 128 + lane * 4;
        atomicAdd(dst + 0, w * f0.x);
        atomicAdd(dst + 1, w * f0.y);
        atomicAdd(dst + 2, w * f1.x);
        atomicAdd(dst + 3, w * f1.y);
    }
}

// ---------------------------------------------------------------------------
// node kernel: normalizes aggr by denom at gather.
// smem: sA 33792 | sB 33792 | sW 24576 = 92160 B
// ---------------------------------------------------------------------------
__global__ __launch_bounds__(256, 2)
void node_kernel(
    const float* __restrict__ nodes,
    const float* __restrict__ ub1, const float* __restrict__ ub2,
    const float* __restrict__ ub3, float* __restrict__ out, int N)
{
    extern __shared__ unsigned char smem[];
    __half* sA = (__half*)smem;                    // stride 264
    __half* sB = (__half*)(smem + 33792);
    unsigned char* sW = smem + 67584;

    const int tid = threadIdx.x, lane = tid & 31, warp = tid >> 5;
    const int n0 = blockIdx.x * 64;

#pragma unroll
    for (int i = 0; i < 8; i++) {
        int e = warp * 8 + i;
        int n = n0 + e;
        __half* dst = sA + e * 264;
        if (n < N) {
            float4 v0 = *(const float4*)(nodes + (size_t)n * 128 + lane * 4);
            *(__half2*)(dst + lane * 4)     = __floats2half2_rn(v0.x, v0.y);
            *(__half2*)(dst + lane * 4 + 2) = __floats2half2_rn(v0.z, v0.w);
            float d = g_denom[n];
            float inv = d > 0.f ? 1.f / d : 0.f;
            float4 v1 = *(const float4*)(g_aggr + (size_t)n * 128 + lane * 4);
            *(__half2*)(dst + 128 + lane * 4)     = __floats2half2_rn(inv * v1.x, inv * v1.y);
            *(__half2*)(dst + 128 + lane * 4 + 2) = __floats2half2_rn(inv * v1.z, inv * v1.w);
        } else {
            *(float2*)(dst + lane * 4) = make_float2(0.f, 0.f);
            *(float2*)(dst + 128 + lane * 4) = make_float2(0.f, 0.f);
        }
    }

    mma_layer<256, 256, true , 264, 264>(sA, g_wpack + OFF_UW1, ub1, sB, sW, nullptr, 0, 0);
    mma_layer<256, 256, false, 264, 264>(sB, g_wpack + OFF_UW2, ub2, sA, sW, nullptr, 0, 0);
    mma_layer<256, 128, false, 264, 136>(sA, g_wpack + OFF_UW3, ub3, sB, sW, out, n0, N);
}

// ---------------------------------------------------------------------------
extern "C" void kernel_launch(void* const* d_in, const int* in_sizes, int n_in,
                              void* d_out, int out_size)
{
    const float* nodes     = (const float*)d_in[0];
    const float* edges     = (const float*)d_in[1];
    const int*   senders   = (const int*)  d_in[2];
    const int*   receivers = (const int*)  d_in[3];
    const float* mw1 = (const float*)d_in[4];  const float* mb1 = (const float*)d_in[5];
    const float* mw2 = (const float*)d_in[6];  const float* mb2 = (const float*)d_in[7];
    const float* mw3 = (const float*)d_in[8];  const float* mb3 = (const float*)d_in[9];
    const float* aw1 = (const float*)d_in[10]; const float* ab1 = (const float*)d_in[11];
    const float* aw2 = (const float*)d_in[12]; const float* ab2 = (const float*)d_in[13];
    const float* aw3 = (const float*)d_in[14]; const float* ab3 = (const float*)d_in[15];
    const float* uw1 = (const float*)d_in[16]; const float* ub1 = (const float*)d_in[17];
    const float* uw2 = (const float*)d_in[18]; const float* ub2 = (const float*)d_in[19];
    const float* uw3 = (const float*)d_in[20]; const float* ub3 = (const float*)d_in[21];
    float* out = (float*)d_out;

    const int N = in_sizes[0] / 128;
    const int E = in_sizes[2];

    const int EDGE_SMEM = 96512;
    const int NODE_SMEM = 92160;
    cudaFuncSetAttribute(edge_kernel, cudaFuncAttributeMaxDynamicSharedMemorySize, EDGE_SMEM);
    cudaFuncSetAttribute(node_kernel, cudaFuncAttributeMaxDynamicSharedMemorySize, NODE_SMEM);

    pack_init_kernel<<<(N * 128 + 255) / 256, 256>>>(
        mw1, mw2, mw3, aw1, aw2, uw1, uw2, uw3, N);

    edge_kernel<<<(E + 63) / 64, 256, EDGE_SMEM>>>(
        nodes, edges, senders, receivers,
        mb1, mb2, mb3, ab1, ab2, aw3, ab3, E);

    node_kernel<<<(N + 63) / 64, 256, NODE_SMEM>>>(
        nodes, ub1, ub2, ub3, out, N);
}

// round 13
// speedup vs baseline: 1.6794x; 1.0923x over previous
#include <cuda_runtime.h>
#include <cuda_fp16.h>
#include <cstdint>

#define NMAX 50048
#define EMAX 400000

__device__ float g_denom[NMAX];
__device__ float g_aggr[(size_t)NMAX * 128];
// packed fp16 weights: per 16-K slab, [NOUT][32B] rows, XOR-swizzled halves
__device__ __align__(16) unsigned char g_wpack[729088];

#define OFF_MW1 0u
#define OFF_MW2 139264u
#define OFF_MW3 270336u
#define OFF_AW1 335872u
#define OFF_AW2 368640u
#define OFF_UW1 401408u
#define OFF_UW2 532480u
#define OFF_UW3 663552u

__device__ __forceinline__ uint32_t smem_u32(const void* p) {
    return (uint32_t)__cvta_generic_to_shared(p);
}
__device__ __forceinline__ void ldsm4(uint32_t& r0, uint32_t& r1,
                                      uint32_t& r2, uint32_t& r3, uint32_t a) {
    asm volatile("ldmatrix.sync.aligned.m8n8.x4.shared.b16 {%0,%1,%2,%3}, [%4];"
                 : "=r"(r0), "=r"(r1), "=r"(r2), "=r"(r3) : "r"(a));
}
__device__ __forceinline__ void mma_f16(float c[4],
    uint32_t a0, uint32_t a1, uint32_t a2, uint32_t a3, uint32_t b0, uint32_t b1)
{
    asm volatile(
        "mma.sync.aligned.m16n8k16.row.col.f32.f16.f16.f32 "
        "{%0,%1,%2,%3}, {%4,%5,%6,%7}, {%8,%9}, {%0,%1,%2,%3};"
        : "+f"(c[0]), "+f"(c[1]), "+f"(c[2]), "+f"(c[3])
        : "r"(a0), "r"(a1), "r"(a2), "r"(a3), "r"(b0), "r"(b1));
}

#define WSTAGE 1024
#define WREGION 3072

// B-row swizzled byte offset (32 B rows, halves XOR bit2 of row)
__device__ __forceinline__ uint32_t bswz(int row, int h) {
    return (uint32_t)(row * 32 + ((h ^ ((row >> 2) & 1)) << 4));
}

// ---------------------------------------------------------------------------
// Warp-autonomous fp16 MLP layer over MT*16 rows, 8 warps.
// Each warp owns cols [warp*NW, (warp+1)*NW), NW = NOUT/8, ALL rows.
// Weights: 32B swizzled rows, flat cp.async triple-buffered per warp.
// ---------------------------------------------------------------------------
template<int K, int NOUT, bool RELU, int LDIN, int LDOUT, int MT>
__device__ __forceinline__ void mma_layer(
    const __half* __restrict__ sIn, const unsigned char* __restrict__ Wp,
    const float* __restrict__ Bv, __half* __restrict__ sOut,
    unsigned char* __restrict__ sWbase,
    float* __restrict__ gOut, int row0, int rowlim)
{
    constexpr int NSLAB = K / 16;
    constexpr int NW = NOUT / 8;
    constexpr int NT = NW / 8;
    constexpr int WCH = NW * 2;
    const int tid = threadIdx.x, lane = tid & 31, warp = tid >> 5;
    const int n0 = warp * NW;
    unsigned char* wb = sWbase + warp * WREGION;
    const int g = lane >> 2, tg = lane & 3;
    const int a_row = (lane & 7) + ((lane >> 3) & 1) * 8;
    const int a_k   = (lane >> 4) * 8;
    const int b_n   = ((lane >> 4) & 1) * 8 + (lane & 7);
    const int b_h   = (lane >> 3) & 1;

    auto issue = [&](int s) {
        if (s < NSLAB) {
            const unsigned char* src = Wp + ((size_t)s * NOUT + n0) * 32;
            unsigned char* dst = wb + (s % 3) * WSTAGE;
#pragma unroll
            for (int c = lane; c < WCH; c += 32) {
                uint32_t da = smem_u32(dst + c * 16);
                asm volatile("cp.async.ca.shared.global [%0], [%1], 16;"
                             :: "r"(da), "l"(src + c * 16));
            }
        }
        asm volatile("cp.async.commit_group;");
    };

    issue(0); issue(1); issue(2);
    __syncthreads();   // sIn ready

    float acc[MT][NT][4];
#pragma unroll
    for (int mt = 0; mt < MT; mt++)
#pragma unroll
        for (int nt = 0; nt < NT; nt++)
#pragma unroll
            for (int q = 0; q < 4; q++) acc[mt][nt][q] = 0.f;

    for (int s = 0; s < NSLAB; s++) {
        asm volatile("cp.async.wait_group 2;" ::: "memory");
        __syncwarp();
        const unsigned char* buf = wb + (s % 3) * WSTAGE;
        const int kc = s * 16;
#pragma unroll
        for (int ng = 0; ng < NT / 2; ng++) {
            uint32_t B0, B1, B2, B3;
            ldsm4(B0, B1, B2, B3, smem_u32(buf + bswz(ng * 16 + b_n, b_h)));
#pragma unroll
            for (int mt = 0; mt < MT; mt++) {
                uint32_t A0, A1, A2, A3;
                ldsm4(A0, A1, A2, A3,
                      smem_u32(sIn + (mt * 16 + a_row) * LDIN + kc + a_k));
                mma_f16(acc[mt][2 * ng],     A0, A1, A2, A3, B0, B1);
                mma_f16(acc[mt][2 * ng + 1], A0, A1, A2, A3, B2, B3);
            }
        }
        issue(s + 3);
    }

#pragma unroll
    for (int nt = 0; nt < NT; nt++) {
        int c = n0 + nt * 8 + 2 * tg;
        float b0 = __ldg(Bv + c), b1 = __ldg(Bv + c + 1);
#pragma unroll
        for (int mt = 0; mt < MT; mt++) {
#pragma unroll
            for (int h = 0; h < 2; h++) {
                int r = mt * 16 + g + h * 8;
                float v0 = acc[mt][nt][h * 2 + 0] + b0;
                float v1 = acc[mt][nt][h * 2 + 1] + b1;
                if (RELU) { v0 = fmaxf(v0, 0.f); v1 = fmaxf(v1, 0.f); }
                *(__half2*)(sOut + r * LDOUT + c) = __floats2half2_rn(v0, v1);
                if (gOut != nullptr && row0 + r < rowlim)
                    *(float2*)(gOut + (size_t)(row0 + r) * NOUT + c) =
                        make_float2(v0, v1);
            }
        }
    }
    __syncthreads();
}

// ---------------------------------------------------------------------------
// G2 variant over MT*16 rows: gate dot folded into epilogue.
// ---------------------------------------------------------------------------
template<int K, int LDIN, int MT>
__device__ __forceinline__ void mma_layer_dot(
    const __half* __restrict__ sIn, const unsigned char* __restrict__ Wp,
    const float* __restrict__ Bv, const float* __restrict__ aw3,
    float* __restrict__ sdot, unsigned char* __restrict__ sWbase)
{
    constexpr int NOUT = 128, NSLAB = K / 16, NW = 16, NT = 2, WCH = NW * 2;
    const int tid = threadIdx.x, lane = tid & 31, warp = tid >> 5;
    const int n0 = warp * NW;
    unsigned char* wb = sWbase + warp * WREGION;
    const int g = lane >> 2, tg = lane & 3;
    const int a_row = (lane & 7) + ((lane >> 3) & 1) * 8;
    const int a_k   = (lane >> 4) * 8;
    const int b_n   = ((lane >> 4) & 1) * 8 + (lane & 7);
    const int b_h   = (lane >> 3) & 1;

    auto issue = [&](int s) {
        if (s < NSLAB) {
            const unsigned char* src = Wp + ((size_t)s * NOUT + n0) * 32;
            unsigned char* dst = wb + (s % 3) * WSTAGE;
#pragma unroll
            for (int c = lane; c < WCH; c += 32) {
                uint32_t da = smem_u32(dst + c * 16);
                asm volatile("cp.async.ca.shared.global [%0], [%1], 16;"
                             :: "r"(da), "l"(src + c * 16));
            }
        }
        asm volatile("cp.async.commit_group;");
    };

    issue(0); issue(1); issue(2);
    __syncthreads();

    float acc[MT][NT][4];
#pragma unroll
    for (int mt = 0; mt < MT; mt++)
#pragma unroll
        for (int nt = 0; nt < NT; nt++)
#pragma unroll
            for (int q = 0; q < 4; q++) acc[mt][nt][q] = 0.f;

    for (int s = 0; s < NSLAB; s++) {
        asm volatile("cp.async.wait_group 2;" ::: "memory");
        __syncwarp();
        const unsigned char* buf = wb + (s % 3) * WSTAGE;
        const int kc = s * 16;
        uint32_t B0, B1, B2, B3;
        ldsm4(B0, B1, B2, B3, smem_u32(buf + bswz(b_n, b_h)));
#pragma unroll
        for (int mt = 0; mt < MT; mt++) {
            uint32_t A0, A1, A2, A3;
            ldsm4(A0, A1, A2, A3,
                  smem_u32(sIn + (mt * 16 + a_row) * LDIN + kc + a_k));
            mma_f16(acc[mt][0], A0, A1, A2, A3, B0, B1);
            mma_f16(acc[mt][1], A0, A1, A2, A3, B2, B3);
        }
        issue(s + 3);
    }

    float dp[MT][2];
#pragma unroll
    for (int mt = 0; mt < MT; mt++) { dp[mt][0] = 0.f; dp[mt][1] = 0.f; }
#pragma unroll
    for (int nt = 0; nt < NT; nt++) {
        int c = n0 + nt * 8 + 2 * tg;
        float b0 = __ldg(Bv + c), b1 = __ldg(Bv + c + 1);
        float a0 = __ldg(aw3 + c), a1 = __ldg(aw3 + c + 1);
#pragma unroll
        for (int mt = 0; mt < MT; mt++) {
#pragma unroll
            for (int h = 0; h < 2; h++) {
                float v0 = acc[mt][nt][h * 2 + 0] + b0;
                float v1 = acc[mt][nt][h * 2 + 1] + b1;
                dp[mt][h] += v0 * a0 + v1 * a1;
            }
        }
    }
#pragma unroll
    for (int mt = 0; mt < MT; mt++)
#pragma unroll
        for (int h = 0; h < 2; h++) {
            dp[mt][h] += __shfl_xor_sync(0xffffffffu, dp[mt][h], 1);
            dp[mt][h] += __shfl_xor_sync(0xffffffffu, dp[mt][h], 2);
            if (tg == 0) {
                int r = mt * 16 + g + h * 8;
                sdot[r * 8 + warp] = dp[mt][h];
            }
        }
    __syncthreads();
}

// ---------------------------------------------------------------------------
// Fused pack + init kernel. Swizzled 32B-row layout.
// ---------------------------------------------------------------------------
__device__ __forceinline__ void pack_one(const float* src, int idx, int N,
                                         unsigned int off) {
    int k = idx / N, n = idx - k * N;
    int s = k >> 4, h = (k >> 3) & 1, e = k & 7;
    uint32_t b = off + (uint32_t)(s * N + n) * 32u
               + (uint32_t)((h ^ ((n >> 2) & 1)) << 4) + (uint32_t)(e * 2);
    *(__half*)(g_wpack + b) = __float2half_rn(src[idx]);
}
__global__ void pack_init_kernel(
    const float* __restrict__ mw1, const float* __restrict__ mw2,
    const float* __restrict__ mw3, const float* __restrict__ aw1,
    const float* __restrict__ aw2, const float* __restrict__ uw1,
    const float* __restrict__ uw2, const float* __restrict__ uw3, int N)
{
    int idx = blockIdx.x * blockDim.x + threadIdx.x;
    if      (idx <  69632) pack_one(mw1, idx,          256, OFF_MW1);
    else if (idx < 135168) pack_one(mw2, idx -  69632, 256, OFF_MW2);
    else if (idx < 167936) pack_one(mw3, idx - 135168, 128, OFF_MW3);
    else if (idx < 184320) pack_one(aw1, idx - 167936, 128, OFF_AW1);
    else if (idx < 200704) pack_one(aw2, idx - 184320, 128, OFF_AW2);
    else if (idx < 266240) pack_one(uw1, idx - 200704, 256, OFF_UW1);
    else if (idx < 331776) pack_one(uw2, idx - 266240, 256, OFF_UW2);
    else if (idx < 364544) pack_one(uw3, idx - 331776, 128, OFF_UW3);
    if (idx < N * 128) g_aggr[idx] = 0.f;
    if (idx < N) g_denom[idx] = 0.f;
}

// ---------------------------------------------------------------------------
// edge kernel: 128 edges/CTA (halves weight L2 traffic). 256 threads.
// smem: sA 71680 | sB 67584 | sW 24576 | sdot 4096 | swexp 512 = 168448 B
// ---------------------------------------------------------------------------
__global__ __launch_bounds__(256, 1)
void edge_kernel(
    const float* __restrict__ nodes, const float* __restrict__ edges,
    const int* __restrict__ senders, const int* __restrict__ receivers,
    const float* __restrict__ b1, const float* __restrict__ b2,
    const float* __restrict__ b3, const float* __restrict__ ab1,
    const float* __restrict__ ab2,
    const float* __restrict__ aw3, const float* __restrict__ ab3, int E)
{
    extern __shared__ unsigned char smem[];
    __half* sA = (__half*)smem;                    // stride 280 (or 136)
    __half* sB = (__half*)(smem + 71680);          // stride 264 (or 136)
    unsigned char* sW = smem + 139264;
    float* sdot = (float*)(smem + 163840);         // [128][8]
    float* swexp = (float*)(smem + 167936);        // [128]

    const int tid = threadIdx.x, lane = tid & 31, warp = tid >> 5;
    const int e0 = blockIdx.x * 128;

#pragma unroll
    for (int i = 0; i < 16; i++) {
        int e = warp * 16 + i;
        int eg = e0 + e;
        int egc = eg < E ? eg : E - 1;
        int s = senders[egc], r = receivers[egc];
        __half* dst = sA + e * 280;
        if (lane < 4) {
            float4 v = *(const float4*)(edges + (size_t)egc * 16 + lane * 4);
            *(__half2*)(dst + lane * 4)     = __floats2half2_rn(v.x, v.y);
            *(__half2*)(dst + lane * 4 + 2) = __floats2half2_rn(v.z, v.w);
        }
        float4 vs = *(const float4*)(nodes + (size_t)s * 128 + lane * 4);
        *(__half2*)(dst + 16 + lane * 4)     = __floats2half2_rn(vs.x, vs.y);
        *(__half2*)(dst + 16 + lane * 4 + 2) = __floats2half2_rn(vs.z, vs.w);
        float4 vr = *(const float4*)(nodes + (size_t)r * 128 + lane * 4);
        *(__half2*)(dst + 144 + lane * 4)     = __floats2half2_rn(vr.x, vr.y);
        *(__half2*)(dst + 144 + lane * 4 + 2) = __floats2half2_rn(vr.z, vr.w);
    }

    mma_layer<272, 256, true , 280, 264, 8>(sA, g_wpack + OFF_MW1, b1, sB, sW, nullptr, 0, 0);
    mma_layer<256, 256, false, 264, 280, 8>(sB, g_wpack + OFF_MW2, b2, sA, sW, nullptr, 0, 0);
    mma_layer<256, 128, false, 280, 136, 8>(sA, g_wpack + OFF_MW3, b3, sB, sW, nullptr, 0, 0);
    mma_layer<128, 128, true , 136, 136, 8>(sB, g_wpack + OFF_AW1, ab1, sA, sW, nullptr, 0, 0);
    mma_layer_dot<128, 136, 8>(sA, g_wpack + OFF_AW2, ab2, aw3, sdot, sW);

    // finalize gates: w = exp(gate) (max-free softmax)
    if (tid < 128) {
        int eg = e0 + tid;
        float w = 0.f;
        if (eg < E) {
            float gate = __ldg(ab3);
#pragma unroll
            for (int j = 0; j < 8; j++) gate += sdot[tid * 8 + j];
            w = expf(gate);
            atomicAdd(&g_denom[receivers[eg]], w);
        }
        swexp[tid] = w;
    }
    __syncthreads();

    // scatter: aggr[recv] += w * msg (vector red, fp16 msgs in sB stride 136)
#pragma unroll
    for (int i = 0; i < 16; i++) {
        int e = warp * 16 + i;
        int eg = e0 + e;
        if (eg >= E) continue;
        float w = swexp[e];
        int r = receivers[eg];
        __half2 p0 = *(__half2*)(sB + e * 136 + lane * 4);
        __half2 p1 = *(__half2*)(sB + e * 136 + lane * 4 + 2);
        float2 f0 = __half22float2(p0), f1 = __half22float2(p1);
        float* dst = g_aggr + (size_t)r * 128 + lane * 4;
        asm volatile("red.global.add.v4.f32 [%0], {%1, %2, %3, %4};"
                     :: "l"(dst), "f"(w * f0.x), "f"(w * f0.y),
                        "f"(w * f1.x), "f"(w * f1.y) : "memory");
    }
}

// ---------------------------------------------------------------------------
// node kernel (unchanged 64-row/2-CTA config): normalizes aggr at gather.
// smem: sA 33792 | sB 33792 | sW 24576 = 92160 B
// ---------------------------------------------------------------------------
__global__ __launch_bounds__(256, 2)
void node_kernel(
    const float* __restrict__ nodes,
    const float* __restrict__ ub1, const float* __restrict__ ub2,
    const float* __restrict__ ub3, float* __restrict__ out, int N)
{
    extern __shared__ unsigned char smem[];
    __half* sA = (__half*)smem;                    // stride 264
    __half* sB = (__half*)(smem + 33792);
    unsigned char* sW = smem + 67584;

    const int tid = threadIdx.x, lane = tid & 31, warp = tid >> 5;
    const int n0 = blockIdx.x * 64;

#pragma unroll
    for (int i = 0; i < 8; i++) {
        int e = warp * 8 + i;
        int n = n0 + e;
        __half* dst = sA + e * 264;
        if (n < N) {
            float4 v0 = *(const float4*)(nodes + (size_t)n * 128 + lane * 4);
            *(__half2*)(dst + lane * 4)     = __floats2half2_rn(v0.x, v0.y);
            *(__half2*)(dst + lane * 4 + 2) = __floats2half2_rn(v0.z, v0.w);
            float d = g_denom[n];
            float inv = d > 0.f ? 1.f / d : 0.f;
            float4 v1 = *(const float4*)(g_aggr + (size_t)n * 128 + lane * 4);
            *(__half2*)(dst + 128 + lane * 4)     = __floats2half2_rn(inv * v1.x, inv * v1.y);
            *(__half2*)(dst + 128 + lane * 4 + 2) = __floats2half2_rn(inv * v1.z, inv * v1.w);
        } else {
            *(float2*)(dst + lane * 4) = make_float2(0.f, 0.f);
            *(float2*)(dst + 128 + lane * 4) = make_float2(0.f, 0.f);
        }
    }

    mma_layer<256, 256, true , 264, 264, 4>(sA, g_wpack + OFF_UW1, ub1, sB, sW, nullptr, 0, 0);
    mma_layer<256, 256, false, 264, 264, 4>(sB, g_wpack + OFF_UW2, ub2, sA, sW, nullptr, 0, 0);
    mma_layer<256, 128, false, 264, 136, 4>(sA, g_wpack + OFF_UW3, ub3, sB, sW, out, n0, N);
}

// ---------------------------------------------------------------------------
extern "C" void kernel_launch(void* const* d_in, const int* in_sizes, int n_in,
                              void* d_out, int out_size)
{
    const float* nodes     = (const float*)d_in[0];
    const float* edges     = (const float*)d_in[1];
    const int*   senders   = (const int*)  d_in[2];
    const int*   receivers = (const int*)  d_in[3];
    const float* mw1 = (const float*)d_in[4];  const float* mb1 = (const float*)d_in[5];
    const float* mw2 = (const float*)d_in[6];  const float* mb2 = (const float*)d_in[7];
    const float* mw3 = (const float*)d_in[8];  const float* mb3 = (const float*)d_in[9];
    const float* aw1 = (const float*)d_in[10]; const float* ab1 = (const float*)d_in[11];
    const float* aw2 = (const float*)d_in[12]; const float* ab2 = (const float*)d_in[13];
    const float* aw3 = (const float*)d_in[14]; const float* ab3 = (const float*)d_in[15];
    const float* uw1 = (const float*)d_in[16]; const float* ub1 = (const float*)d_in[17];
    const float* uw2 = (const float*)d_in[18]; const float* ub2 = (const float*)d_in[19];
    const float* uw3 = (const float*)d_in[20]; const float* ub3 = (const float*)d_in[21];
    float* out = (float*)d_out;

    const int N = in_sizes[0] / 128;
    const int E = in_sizes[2];

    const int EDGE_SMEM = 168448;
    const int NODE_SMEM = 92160;
    cudaFuncSetAttribute(edge_kernel, cudaFuncAttributeMaxDynamicSharedMemorySize, EDGE_SMEM);
    cudaFuncSetAttribute(node_kernel, cudaFuncAttributeMaxDynamicSharedMemorySize, NODE_SMEM);

    pack_init_kernel<<<(N * 128 + 255) / 256, 256>>>(
        mw1, mw2, mw3, aw1, aw2, uw1, uw2, uw3, N);

    edge_kernel<<<(E + 127) / 128, 256, EDGE_SMEM>>>(
        nodes, edges, senders, receivers,
        mb1, mb2, mb3, ab1, ab2, aw3, ab3, E);

    node_kernel<<<(N + 63) / 64, 256, NODE_SMEM>>>(
        nodes, ub1, ub2, ub3, out, N);
}